// round 8
// baseline (speedup 1.0000x reference)
#include <cuda_runtime.h>
#include <cstdint>
#include <cstddef>

#define S_LEN 512
#define BATCH 32
#define G4    1024
#define MROWS (S_LEN*BATCH)
#define NEGV  -10000.0f

// ---------------- device scratch ----------------
__device__ float g_x[MROWS*256];
__device__ float g_pre_f[MROWS*G4];
__device__ float g_pre_b[MROWS*G4];
__device__ float g_hf[MROWS*256];
__device__ float g_hb[MROWS*256];
__device__ float g_emit[MROWS*16];

// ---------------- f32x2 packed helpers ----------------
__device__ __forceinline__ void fma2(unsigned long long& d, unsigned long long a,
                                     unsigned long long b) {
    asm("fma.rn.f32x2 %0, %1, %2, %0;" : "+l"(d) : "l"(a), "l"(b));
}
__device__ __forceinline__ unsigned long long pk2(float lo, float hi) {
    unsigned long long r;
    asm("mov.b64 %0, {%1, %2};" : "=l"(r) : "f"(lo), "f"(hi));
    return r;
}
__device__ __forceinline__ void up2(unsigned long long v, float& lo, float& hi) {
    asm("mov.b64 {%0, %1}, %2;" : "=f"(lo), "=f"(hi) : "l"(v));
}

__device__ __forceinline__ float tanh_ap(float x) {
    float y;
    asm("tanh.approx.f32 %0, %1;" : "=f"(y) : "f"(x));
    return y;
}
__device__ __forceinline__ float sigf(float x) {
    return fmaf(0.5f, tanh_ap(0.5f * x), 0.5f);
}

// mbarrier ops
__device__ __forceinline__ void mbar_init(uint32_t addr, uint32_t count) {
    asm volatile("mbarrier.init.shared.b64 [%0], %1;" :: "r"(addr), "r"(count) : "memory");
}
__device__ __forceinline__ void mbar_arrive_cluster(uint32_t raddr) {
    asm volatile("mbarrier.arrive.release.cluster.shared::cluster.b64 _, [%0];"
                 :: "r"(raddr) : "memory");
}
__device__ __forceinline__ void mbar_wait(uint32_t mbar, uint32_t par) {
    uint32_t done;
    asm volatile("{\n\t.reg .pred p;\n\t"
        "mbarrier.try_wait.parity.acquire.cluster.shared::cta.b64 p, [%1], %2, 0x989680;\n\t"
        "selp.b32 %0, 1, 0, p;\n\t}"
        : "=r"(done) : "r"(mbar), "r"(par) : "memory");
    while (!done) {
        asm volatile("{\n\t.reg .pred p;\n\t"
            "mbarrier.try_wait.parity.acquire.cluster.shared::cta.b64 p, [%1], %2, 0x989680;\n\t"
            "selp.b32 %0, 1, 0, p;\n\t}"
            : "=r"(done) : "r"(mbar), "r"(par) : "memory");
    }
}

// ---------------- kernel 1: embedding gather ----------------
__global__ void __launch_bounds__(64) k_gather(const int* __restrict__ tokens,
                                               const float* __restrict__ emb) {
    int bid = blockIdx.x;              // = s*32 + b
    int s = bid >> 5, b = bid & 31;
    int tok = tokens[b * S_LEN + s];
    const float4* src = (const float4*)(emb + (size_t)tok * 256);
    float4* dst = (float4*)(g_x + (size_t)bid * 256);
    dst[threadIdx.x] = src[threadIdx.x];
}

// ---------------- profiler-steering no-op ----------------
__global__ void k_probe() {}

// ---------------- kernel 2: input GEMM (f32x2, ping-pong smem + reg prefetch) ----------------
__global__ void __launch_bounds__(256) k_gemm(const float* __restrict__ Wf,
                                              const float* __restrict__ bif,
                                              const float* __restrict__ bhf,
                                              const float* __restrict__ Wb,
                                              const float* __restrict__ bib,
                                              const float* __restrict__ bhb) {
    const int dir = blockIdx.z;
    const float* __restrict__ W  = dir ? Wb  : Wf;
    const float* __restrict__ b1 = dir ? bib : bif;
    const float* __restrict__ b2 = dir ? bhb : bhf;
    float* __restrict__ out = dir ? g_pre_b : g_pre_f;

    __shared__ float As[2][8 * 128];
    __shared__ float Bs[2][8 * 128];
    const int tid = threadIdx.x;
    const int m0 = blockIdx.y * 128, n0 = blockIdx.x * 128;
    const int lrow = tid >> 1, lk4 = (tid & 1) * 4;
    const float* aptr = g_x + (size_t)(m0 + lrow) * 256 + lk4;
    const float* bptr = W   + (size_t)(n0 + lrow) * 256 + lk4;
    const int ty = tid >> 4, tx = tid & 15;

    unsigned long long acc2[8][4];
#pragma unroll
    for (int i = 0; i < 8; i++)
#pragma unroll
        for (int j = 0; j < 4; j++) acc2[i][j] = 0ull;

    // prologue: stage tile 0
    {
        float4 av = *(const float4*)(aptr);
        float4 bv = *(const float4*)(bptr);
        As[0][(lk4 + 0) * 128 + lrow] = av.x; As[0][(lk4 + 1) * 128 + lrow] = av.y;
        As[0][(lk4 + 2) * 128 + lrow] = av.z; As[0][(lk4 + 3) * 128 + lrow] = av.w;
        Bs[0][(lk4 + 0) * 128 + lrow] = bv.x; Bs[0][(lk4 + 1) * 128 + lrow] = bv.y;
        Bs[0][(lk4 + 2) * 128 + lrow] = bv.z; Bs[0][(lk4 + 3) * 128 + lrow] = bv.w;
    }
    __syncthreads();

    for (int it = 0; it < 32; ++it) {
        const int buf = it & 1;
        float4 av, bv;
        const bool more = (it + 1 < 32);
        if (more) {
            av = *(const float4*)(aptr + (it + 1) * 8);
            bv = *(const float4*)(bptr + (it + 1) * 8);
        }
#pragma unroll
        for (int k = 0; k < 8; k++) {
            float4 a0 = *(const float4*)&As[buf][k * 128 + ty * 8];
            float4 a1 = *(const float4*)&As[buf][k * 128 + ty * 8 + 4];
            ulonglong2 bq0 = *(const ulonglong2*)&Bs[buf][k * 128 + tx * 8];
            ulonglong2 bq1 = *(const ulonglong2*)&Bs[buf][k * 128 + tx * 8 + 4];
            unsigned long long ad[8];
            ad[0] = pk2(a0.x, a0.x); ad[1] = pk2(a0.y, a0.y);
            ad[2] = pk2(a0.z, a0.z); ad[3] = pk2(a0.w, a0.w);
            ad[4] = pk2(a1.x, a1.x); ad[5] = pk2(a1.y, a1.y);
            ad[6] = pk2(a1.z, a1.z); ad[7] = pk2(a1.w, a1.w);
            unsigned long long bp[4] = {bq0.x, bq0.y, bq1.x, bq1.y};
#pragma unroll
            for (int i = 0; i < 8; i++)
#pragma unroll
                for (int jp = 0; jp < 4; jp++) fma2(acc2[i][jp], ad[i], bp[jp]);
        }
        if (more) {
            const int nb = buf ^ 1;
            As[nb][(lk4 + 0) * 128 + lrow] = av.x; As[nb][(lk4 + 1) * 128 + lrow] = av.y;
            As[nb][(lk4 + 2) * 128 + lrow] = av.z; As[nb][(lk4 + 3) * 128 + lrow] = av.w;
            Bs[nb][(lk4 + 0) * 128 + lrow] = bv.x; Bs[nb][(lk4 + 1) * 128 + lrow] = bv.y;
            Bs[nb][(lk4 + 2) * 128 + lrow] = bv.z; Bs[nb][(lk4 + 3) * 128 + lrow] = bv.w;
        }
        __syncthreads();
    }
#pragma unroll
    for (int i = 0; i < 8; i++) {
        int m = m0 + ty * 8 + i;
#pragma unroll
        for (int jp = 0; jp < 2; jp++) {
            int n = n0 + tx * 8 + jp * 4;
            float v0, v1, v2, v3;
            up2(acc2[i][jp * 2 + 0], v0, v1);
            up2(acc2[i][jp * 2 + 1], v2, v3);
            float4 v;
            v.x = v0 + b1[n + 0] + b2[n + 0];
            v.y = v1 + b1[n + 1] + b2[n + 1];
            v.z = v2 + b1[n + 2] + b2[n + 2];
            v.w = v3 + b1[n + 3] + b2[n + 3];
            *(float4*)(out + (size_t)m * G4 + n) = v;
        }
    }
}

// ---------------- kernel 3: LSTM recurrence (R6 structure + hierarchical mbarrier) ----------------
// smem floats: [0, 32768)       Wh transposed: w[k*128 + lr]
//              [32768, 34816)   hbuf: 2 phase x 4 batch x 256
//              [34816, 38912)   zred: 8 kg x 4 batch x 128 rows
// byte 155648: mbarrier (8B)
#define R5_W     0
#define R5_HBUF  32768
#define R5_ZRED  34816
#define R5_MBARB 155648
#define R5_SMEMB 155664

__global__ void __launch_bounds__(256, 1) __cluster_dims__(8, 1, 1)
k_recur(const float* __restrict__ Wh_f, const float* __restrict__ Wh_b) {
    extern __shared__ float sm[];
    const int tid = threadIdx.x;
    uint32_t r;
    asm("mov.u32 %0, %%cluster_ctarank;" : "=r"(r));
    const int c   = blockIdx.x >> 3;   // cluster id 0..15
    const int dir = c >> 3;            // 0 fwd, 1 bwd
    const int bg  = c & 7;             // batch group of 4
    const float* __restrict__ Wh   = dir ? Wh_b   : Wh_f;
    const float* __restrict__ preb = dir ? g_pre_b : g_pre_f;
    float* __restrict__ hout       = dir ? g_hb   : g_hf;

    const uint32_t smem_u32 = (uint32_t)__cvta_generic_to_shared(sm);
    const uint32_t mbar = smem_u32 + R5_MBARB;
    const uint32_t hbuf_u32 = smem_u32 + R5_HBUF * 4;

    // remote addresses (uniform)
    uint32_t rhb[8], rmb[8];
#pragma unroll
    for (int rr = 0; rr < 8; ++rr) {
        asm("mapa.shared::cluster.u32 %0, %1, %2;" : "=r"(rhb[rr]) : "r"(hbuf_u32), "r"(rr));
        asm("mapa.shared::cluster.u32 %0, %1, %2;" : "=r"(rmb[rr]) : "r"(mbar), "r"(rr));
    }

    // load Wh slice transposed: w[k*128 + lr] = Wh[(q*256 + r*32 + uu)*256 + k]
    for (int idx = tid; idx < 128 * 64; idx += 256) {      // idx over (lr, k4)
        int lr = idx >> 6, k4 = (idx & 63) << 2;
        int q = lr >> 5, uu = lr & 31;
        float4 w = *(const float4*)(Wh + (size_t)((q << 8) + ((int)r << 5) + uu) * 256 + k4);
        sm[R5_W + (k4 + 0) * 128 + lr] = w.x;
        sm[R5_W + (k4 + 1) * 128 + lr] = w.y;
        sm[R5_W + (k4 + 2) * 128 + lr] = w.z;
        sm[R5_W + (k4 + 3) * 128 + lr] = w.w;
    }
    for (int i = tid; i < 2048; i += 256) sm[R5_HBUF + i] = 0.f;
    if (tid == 0) mbar_init(mbar, 8);   // one arrival per CTA
    __syncthreads();
    asm volatile("barrier.cluster.arrive.aligned;" ::: "memory");
    asm volatile("barrier.cluster.wait.aligned;" ::: "memory");

    const int kg = tid >> 5, ot = tid & 31;     // z-phase: lane ot owns rows 4ot..4ot+3
    const int gb = tid >> 5, guu = tid & 31;    // gate-phase (tid<128)
    const int bglob = bg * 4 + gb;
    float cstate = 0.f;
    int cur = 0;

    float pre4[4] = {0.f, 0.f, 0.f, 0.f};
    if (tid < 128) {
        const int s0 = dir ? (S_LEN - 1) : 0;
        const float* pp = preb + (size_t)(s0 * BATCH + bglob) * G4 + ((int)r << 5) + guu;
        pre4[0] = pp[0]; pre4[1] = pp[256]; pre4[2] = pp[512]; pre4[3] = pp[768];
    }
    const uint32_t hoffb = (uint32_t)((gb * 256 + ((int)r << 5) + guu) * 4);

    for (int t = 0; t < S_LEN; ++t) {
        const int s = dir ? (S_LEN - 1 - t) : t;
        if (t) mbar_wait(mbar, (t - 1) & 1);   // all CTAs' step t-1 arrivals landed

        // z partials: lane ot accumulates rows 4ot..4ot+3 (f32x2 row pairs) x 4 batches
        const float* hc = sm + R5_HBUF + cur * 1024;
        const float* wbase = sm + R5_W + (ot << 2);
        unsigned long long acc0[4], acc1[4];
#pragma unroll
        for (int b = 0; b < 4; ++b) { acc0[b] = 0ull; acc1[b] = 0ull; }

#pragma unroll
        for (int kb = 0; kb < 32; kb += 4) {
            const int k = kg * 32 + kb;
            float4 h0 = *(const float4*)(hc + k);
            float4 h1 = *(const float4*)(hc + 256 + k);
            float4 h2 = *(const float4*)(hc + 512 + k);
            float4 h3 = *(const float4*)(hc + 768 + k);
            float ha[4][4] = {{h0.x, h1.x, h2.x, h3.x},
                              {h0.y, h1.y, h2.y, h3.y},
                              {h0.z, h1.z, h2.z, h3.z},
                              {h0.w, h1.w, h2.w, h3.w}};
#pragma unroll
            for (int j = 0; j < 4; ++j) {
                ulonglong2 w = *(const ulonglong2*)(wbase + (k + j) * 128);
#pragma unroll
                for (int b = 0; b < 4; ++b) {
                    unsigned long long hs = pk2(ha[j][b], ha[j][b]);
                    fma2(acc0[b], w.x, hs);
                    fma2(acc1[b], w.y, hs);
                }
            }
        }
        {
            float* zb = sm + R5_ZRED + kg * 512 + (ot << 2);
#pragma unroll
            for (int b = 0; b < 4; ++b) {
                ulonglong2 v; v.x = acc0[b]; v.y = acc1[b];
                *(ulonglong2*)(zb + b * 128) = v;
            }
        }
        __syncthreads();

        if (tid < 128) {
            float z0 = pre4[0], z1 = pre4[1], z2 = pre4[2], z3 = pre4[3];
#pragma unroll
            for (int kk = 0; kk < 8; ++kk) {
                const float* zb = sm + R5_ZRED + kk * 512 + gb * 128;
                z0 += zb[guu]; z1 += zb[32 + guu]; z2 += zb[64 + guu]; z3 += zb[96 + guu];
            }
            float ig = sigf(z0), fg = sigf(z1);
            float gg = tanh_ap(z2), og = sigf(z3);
            cstate = fg * cstate + ig * gg;
            float hval = og * tanh_ap(cstate);
            hout[(size_t)(s * BATCH + bglob) * 256 + ((int)r << 5) + guu] = hval;

            float hnext = __shfl_down_sync(0xffffffffu, hval, 1);
            if ((guu & 1) == 0) {
                unsigned long long pk =
                    ((unsigned long long)__float_as_uint(hnext) << 32) | __float_as_uint(hval);
                const uint32_t off = ((uint32_t)(cur ^ 1) << 12) + hoffb;
#pragma unroll
                for (int rr = 0; rr < 8; ++rr)
                    asm volatile("st.shared::cluster.b64 [%0], %1;"
                                 :: "r"(rhb[rr] + off), "l"(pk) : "memory");
            }
        }
        __syncthreads();   // all producers' remote stores precede tid0's release-arrive

        if (tid == 0) {
#pragma unroll
            for (int rr = 0; rr < 8; ++rr) mbar_arrive_cluster(rmb[rr]);
        }

        // prefetch next step's pre under the barrier window
        if (tid < 128 && t + 1 < S_LEN) {
            const int s2 = dir ? (S_LEN - 2 - t) : (t + 1);
            const float* pp = preb + (size_t)(s2 * BATCH + bglob) * G4 + ((int)r << 5) + guu;
            pre4[0] = pp[0]; pre4[1] = pp[256]; pre4[2] = pp[512]; pre4[3] = pp[768];
        }
        cur ^= 1;
    }
    mbar_wait(mbar, (S_LEN - 1) & 1);   // drain before exit
}

// ---------------- kernel 4: emissions (256 thr: hf/hb split + smem reduce) ----------------
__global__ void __launch_bounds__(256) k_emit(const float* __restrict__ Wt,
                                              const float* __restrict__ bt) {
    __shared__ float WtT[8192];   // [k][t], 512 x 16
    __shared__ float part[2048];  // 128 rows x 16 tags
    const int tid = threadIdx.x;
    for (int i = tid; i < 8192; i += 256) {
        int k = i >> 4, t = i & 15;
        WtT[i] = Wt[t * 512 + k];
    }
    __syncthreads();

    const int half = tid >> 7, rt = tid & 127;
    const size_t m = (size_t)blockIdx.x * 128 + rt;
    const float4* rr = (const float4*)((half ? g_hb : g_hf) + m * 256);
    const float* wb = &WtT[half * 4096];
    float acc[16];
#pragma unroll
    for (int t = 0; t < 16; ++t) acc[t] = 0.f;

#pragma unroll 4
    for (int k4 = 0; k4 < 64; ++k4) {
        float4 f = rr[k4];
        float fa[4] = {f.x, f.y, f.z, f.w};
#pragma unroll
        for (int j = 0; j < 4; ++j) {
            const float* wrow = &wb[(k4 * 4 + j) * 16];
            float4 w0 = *(const float4*)(wrow + 0);
            float4 w1 = *(const float4*)(wrow + 4);
            float4 w2 = *(const float4*)(wrow + 8);
            float4 w3 = *(const float4*)(wrow + 12);
            acc[0]  += fa[j] * w0.x; acc[1]  += fa[j] * w0.y; acc[2]  += fa[j] * w0.z; acc[3]  += fa[j] * w0.w;
            acc[4]  += fa[j] * w1.x; acc[5]  += fa[j] * w1.y; acc[6]  += fa[j] * w1.z; acc[7]  += fa[j] * w1.w;
            acc[8]  += fa[j] * w2.x; acc[9]  += fa[j] * w2.y; acc[10] += fa[j] * w2.z; acc[11] += fa[j] * w2.w;
            acc[12] += fa[j] * w3.x; acc[13] += fa[j] * w3.y; acc[14] += fa[j] * w3.z; acc[15] += fa[j] * w3.w;
        }
    }
    if (half == 0) {
#pragma unroll
        for (int t = 0; t < 16; t += 4)
            *(float4*)&part[rt * 16 + t] = make_float4(acc[t], acc[t+1], acc[t+2], acc[t+3]);
    }
    __syncthreads();
    if (half == 1) {
        float4* o = (float4*)(g_emit + m * 16);
#pragma unroll
        for (int t = 0; t < 16; t += 4) {
            float4 p = *(const float4*)&part[rt * 16 + t];
            float4 v;
            v.x = acc[t+0] + p.x + bt[t+0];
            v.y = acc[t+1] + p.y + bt[t+1];
            v.z = acc[t+2] + p.z + bt[t+2];
            v.w = acc[t+3] + p.w + bt[t+3];
            o[t >> 2] = v;
        }
    }
}

// ---------------- kernel 5: CRF forward, one block per batch ----------------
__global__ void __launch_bounds__(32) k_crf(const float* __restrict__ trans,
                                            float* __restrict__ out) {
    __shared__ float embuf[512];   // 32 steps x 16 tags
    const int b = blockIdx.x;
    const int lane = threadIdx.x;
    const int tn = lane >> 1;        // target tag
    const int tp0 = (lane & 1) * 8;  // my half of prev tags

    float tr[8];
#pragma unroll
    for (int j = 0; j < 8; ++j) tr[j] = trans[tn * 16 + tp0 + j];

    float al[8];
#pragma unroll
    for (int j = 0; j < 8; ++j) al[j] = ((tp0 + j) == 14) ? 0.f : NEGV;  // START=14

    for (int c = 0; c < 16; ++c) {   // 16 chunks of 32 steps
        for (int i = lane; i < 128; i += 32) {
            int sl = i >> 2, q = i & 3;
            ((float4*)embuf)[i] =
                *(const float4*)(g_emit + ((size_t)((c * 32 + sl) * 32 + b) * 16) + q * 4);
        }
        __syncwarp();

        for (int sl = 0; sl < 32; ++sl) {
            float m8 = -1e30f;
            float sc[8];
#pragma unroll
            for (int j = 0; j < 8; ++j) {
                sc[j] = al[j] + tr[j];
                m8 = fmaxf(m8, sc[j]);
            }
            float m = fmaxf(m8, __shfl_xor_sync(0xffffffffu, m8, 1));
            float e = 0.f;
#pragma unroll
            for (int j = 0; j < 8; ++j) e += __expf(sc[j] - m);
            e += __shfl_xor_sync(0xffffffffu, e, 1);
            float na = m + __logf(e) + embuf[sl * 16 + tn];
#pragma unroll
            for (int j = 0; j < 8; ++j)
                al[j] = __shfl_sync(0xffffffffu, na, (tp0 + j) << 1);
        }
        __syncwarp();
    }

    float m8 = -1e30f;
    float sc[8];
#pragma unroll
    for (int j = 0; j < 8; ++j) {
        sc[j] = al[j] + trans[15 * 16 + tp0 + j];
        m8 = fmaxf(m8, sc[j]);
    }
    float m = fmaxf(m8, __shfl_xor_sync(0xffffffffu, m8, 1));
    float e = 0.f;
#pragma unroll
    for (int j = 0; j < 8; ++j) e += __expf(sc[j] - m);
    e += __shfl_xor_sync(0xffffffffu, e, 1);
    if (lane == 0) out[b] = m + __logf(e);
}

// ---------------- launch ----------------
extern "C" void kernel_launch(void* const* d_in, const int* in_sizes, int n_in,
                              void* d_out, int out_size) {
    (void)in_sizes; (void)n_in; (void)out_size;
    const int*   tokens = (const int*)  d_in[0];
    const float* emb    = (const float*)d_in[1];
    const float* Wi_f   = (const float*)d_in[2];
    const float* Wh_f   = (const float*)d_in[3];
    const float* bi_f   = (const float*)d_in[4];
    const float* bh_f   = (const float*)d_in[5];
    const float* Wi_b   = (const float*)d_in[6];
    const float* Wh_b   = (const float*)d_in[7];
    const float* bi_b   = (const float*)d_in[8];
    const float* bh_b   = (const float*)d_in[9];
    const float* Wt     = (const float*)d_in[10];
    const float* bt     = (const float*)d_in[11];
    const float* trans  = (const float*)d_in[12];
    float* out = (float*)d_out;

    static int configured = 0;
    if (!configured) {
        cudaFuncSetAttribute(k_recur, cudaFuncAttributeMaxDynamicSharedMemorySize, R5_SMEMB);
        configured = 1;
    }

    k_gather<<<MROWS, 64>>>(tokens, emb);
    k_gemm<<<dim3(8, 128, 2), 256>>>(Wi_f, bi_f, bh_f, Wi_b, bi_b, bh_b);
    k_probe<<<1, 32>>>();   // keep k_recur in ncu's profiled slot
    k_recur<<<128, 256, R5_SMEMB>>>(Wh_f, Wh_b);
    k_emit<<<128, 256>>>(Wt, bt);
    k_crf<<<BATCH, 32>>>(trans, out);
}

// round 9
// speedup vs baseline: 1.6333x; 1.6333x over previous
#include <cuda_runtime.h>
#include <cstdint>
#include <cstddef>

#define S_LEN 512
#define BATCH 32
#define G4    1024
#define MROWS (S_LEN*BATCH)
#define NEGV  -10000.0f

// ---------------- device scratch ----------------
__device__ float g_x[MROWS*256];
__device__ float g_pre_f[MROWS*G4];
__device__ float g_pre_b[MROWS*G4];
__device__ float g_hf[MROWS*256];
__device__ float g_hb[MROWS*256];
__device__ float g_emit[MROWS*16];

// ---------------- f32x2 packed helpers ----------------
__device__ __forceinline__ void fma2(unsigned long long& d, unsigned long long a,
                                     unsigned long long b) {
    asm("fma.rn.f32x2 %0, %1, %2, %0;" : "+l"(d) : "l"(a), "l"(b));
}
__device__ __forceinline__ unsigned long long pk2(float lo, float hi) {
    unsigned long long r;
    asm("mov.b64 %0, {%1, %2};" : "=l"(r) : "f"(lo), "f"(hi));
    return r;
}
__device__ __forceinline__ void up2(unsigned long long v, float& lo, float& hi) {
    asm("mov.b64 {%0, %1}, %2;" : "=f"(lo), "=f"(hi) : "l"(v));
}

__device__ __forceinline__ float tanh_ap(float x) {
    float y;
    asm("tanh.approx.f32 %0, %1;" : "=f"(y) : "f"(x));
    return y;
}
__device__ __forceinline__ float sigf(float x) {
    return fmaf(0.5f, tanh_ap(0.5f * x), 0.5f);
}

// ---------------- kernel 1: embedding gather ----------------
__global__ void __launch_bounds__(64) k_gather(const int* __restrict__ tokens,
                                               const float* __restrict__ emb) {
    int bid = blockIdx.x;              // = s*32 + b
    int s = bid >> 5, b = bid & 31;
    int tok = tokens[b * S_LEN + s];
    const float4* src = (const float4*)(emb + (size_t)tok * 256);
    float4* dst = (float4*)(g_x + (size_t)bid * 256);
    dst[threadIdx.x] = src[threadIdx.x];
}

// ---------------- profiler-steering no-op ----------------
__global__ void k_probe() {}

// ---------------- kernel 2: input GEMM (f32x2, ping-pong smem + reg prefetch) ----------------
__global__ void __launch_bounds__(256) k_gemm(const float* __restrict__ Wf,
                                              const float* __restrict__ bif,
                                              const float* __restrict__ bhf,
                                              const float* __restrict__ Wb,
                                              const float* __restrict__ bib,
                                              const float* __restrict__ bhb) {
    const int dir = blockIdx.z;
    const float* __restrict__ W  = dir ? Wb  : Wf;
    const float* __restrict__ b1 = dir ? bib : bif;
    const float* __restrict__ b2 = dir ? bhb : bhf;
    float* __restrict__ out = dir ? g_pre_b : g_pre_f;

    __shared__ float As[2][8 * 128];
    __shared__ float Bs[2][8 * 128];
    const int tid = threadIdx.x;
    const int m0 = blockIdx.y * 128, n0 = blockIdx.x * 128;
    const int lrow = tid >> 1, lk4 = (tid & 1) * 4;
    const float* aptr = g_x + (size_t)(m0 + lrow) * 256 + lk4;
    const float* bptr = W   + (size_t)(n0 + lrow) * 256 + lk4;
    const int ty = tid >> 4, tx = tid & 15;

    unsigned long long acc2[8][4];
#pragma unroll
    for (int i = 0; i < 8; i++)
#pragma unroll
        for (int j = 0; j < 4; j++) acc2[i][j] = 0ull;

    {
        float4 av = *(const float4*)(aptr);
        float4 bv = *(const float4*)(bptr);
        As[0][(lk4 + 0) * 128 + lrow] = av.x; As[0][(lk4 + 1) * 128 + lrow] = av.y;
        As[0][(lk4 + 2) * 128 + lrow] = av.z; As[0][(lk4 + 3) * 128 + lrow] = av.w;
        Bs[0][(lk4 + 0) * 128 + lrow] = bv.x; Bs[0][(lk4 + 1) * 128 + lrow] = bv.y;
        Bs[0][(lk4 + 2) * 128 + lrow] = bv.z; Bs[0][(lk4 + 3) * 128 + lrow] = bv.w;
    }
    __syncthreads();

    for (int it = 0; it < 32; ++it) {
        const int buf = it & 1;
        float4 av, bv;
        const bool more = (it + 1 < 32);
        if (more) {
            av = *(const float4*)(aptr + (it + 1) * 8);
            bv = *(const float4*)(bptr + (it + 1) * 8);
        }
#pragma unroll
        for (int k = 0; k < 8; k++) {
            float4 a0 = *(const float4*)&As[buf][k * 128 + ty * 8];
            float4 a1 = *(const float4*)&As[buf][k * 128 + ty * 8 + 4];
            ulonglong2 bq0 = *(const ulonglong2*)&Bs[buf][k * 128 + tx * 8];
            ulonglong2 bq1 = *(const ulonglong2*)&Bs[buf][k * 128 + tx * 8 + 4];
            unsigned long long ad[8];
            ad[0] = pk2(a0.x, a0.x); ad[1] = pk2(a0.y, a0.y);
            ad[2] = pk2(a0.z, a0.z); ad[3] = pk2(a0.w, a0.w);
            ad[4] = pk2(a1.x, a1.x); ad[5] = pk2(a1.y, a1.y);
            ad[6] = pk2(a1.z, a1.z); ad[7] = pk2(a1.w, a1.w);
            unsigned long long bp[4] = {bq0.x, bq0.y, bq1.x, bq1.y};
#pragma unroll
            for (int i = 0; i < 8; i++)
#pragma unroll
                for (int jp = 0; jp < 4; jp++) fma2(acc2[i][jp], ad[i], bp[jp]);
        }
        if (more) {
            const int nb = buf ^ 1;
            As[nb][(lk4 + 0) * 128 + lrow] = av.x; As[nb][(lk4 + 1) * 128 + lrow] = av.y;
            As[nb][(lk4 + 2) * 128 + lrow] = av.z; As[nb][(lk4 + 3) * 128 + lrow] = av.w;
            Bs[nb][(lk4 + 0) * 128 + lrow] = bv.x; Bs[nb][(lk4 + 1) * 128 + lrow] = bv.y;
            Bs[nb][(lk4 + 2) * 128 + lrow] = bv.z; Bs[nb][(lk4 + 3) * 128 + lrow] = bv.w;
        }
        __syncthreads();
    }
#pragma unroll
    for (int i = 0; i < 8; i++) {
        int m = m0 + ty * 8 + i;
#pragma unroll
        for (int jp = 0; jp < 2; jp++) {
            int n = n0 + tx * 8 + jp * 4;
            float v0, v1, v2, v3;
            up2(acc2[i][jp * 2 + 0], v0, v1);
            up2(acc2[i][jp * 2 + 1], v2, v3);
            float4 v;
            v.x = v0 + b1[n + 0] + b2[n + 0];
            v.y = v1 + b1[n + 1] + b2[n + 1];
            v.z = v2 + b1[n + 2] + b2[n + 2];
            v.w = v3 + b1[n + 3] + b2[n + 3];
            *(float4*)(out + (size_t)m * G4 + n) = v;
        }
    }
}

// ---------------- kernel 3: LSTM recurrence (R6 protocol + pipelined z-loop loads) ----------------
// smem floats: [0, 32768)       Wh transposed: w[k*128 + lr]
//              [32768, 34816)   hbuf: 2 phase x 4 batch x 256
//              [34816, 38912)   zred: 8 kg x 4 batch x 128 rows
#define R3_W     0
#define R3_HBUF  32768
#define R3_ZRED  34816
#define R3_SMEMB (38912 * 4)

__device__ __forceinline__ void cl_arrive() {
    asm volatile("barrier.cluster.arrive.aligned;" ::: "memory");
}
__device__ __forceinline__ void cl_wait() {
    asm volatile("barrier.cluster.wait.aligned;" ::: "memory");
}

__global__ void __launch_bounds__(256, 1) __cluster_dims__(8, 1, 1)
k_recur(const float* __restrict__ Wh_f, const float* __restrict__ Wh_b) {
    extern __shared__ float sm[];
    const int tid = threadIdx.x;
    uint32_t r;
    asm("mov.u32 %0, %%cluster_ctarank;" : "=r"(r));
    const int c   = blockIdx.x >> 3;   // cluster id 0..15
    const int dir = c >> 3;            // 0 fwd, 1 bwd
    const int bg  = c & 7;             // batch group of 4
    const float* __restrict__ Wh   = dir ? Wh_b   : Wh_f;
    const float* __restrict__ preb = dir ? g_pre_b : g_pre_f;
    float* __restrict__ hout       = dir ? g_hb   : g_hf;

    // load Wh slice transposed: w[k*128 + lr] = Wh[(q*256 + r*32 + uu)*256 + k]
    for (int idx = tid; idx < 128 * 64; idx += 256) {      // idx over (lr, k4)
        int lr = idx >> 6, k4 = (idx & 63) << 2;
        int q = lr >> 5, uu = lr & 31;
        float4 w = *(const float4*)(Wh + (size_t)((q << 8) + ((int)r << 5) + uu) * 256 + k4);
        sm[R3_W + (k4 + 0) * 128 + lr] = w.x;
        sm[R3_W + (k4 + 1) * 128 + lr] = w.y;
        sm[R3_W + (k4 + 2) * 128 + lr] = w.z;
        sm[R3_W + (k4 + 3) * 128 + lr] = w.w;
    }
    for (int i = tid; i < 2048; i += 256) sm[R3_HBUF + i] = 0.f;
    __syncthreads();
    cl_arrive(); cl_wait();

    const int kg = tid >> 5, ot = tid & 31;     // z-phase: lane ot owns rows 4ot..4ot+3
    const int gb = tid >> 5, guu = tid & 31;    // gate-phase (tid<128)
    const int bglob = bg * 4 + gb;
    float cstate = 0.f;
    int cur = 0;
    uint32_t hbuf_u32 = (uint32_t)__cvta_generic_to_shared(&sm[R3_HBUF]);

    float pre4[4] = {0.f, 0.f, 0.f, 0.f};
    if (tid < 128) {
        const int s0 = dir ? (S_LEN - 1) : 0;
        const float* pp = preb + (size_t)(s0 * BATCH + bglob) * G4 + ((int)r << 5) + guu;
        pre4[0] = pp[0]; pre4[1] = pp[256]; pre4[2] = pp[512]; pre4[3] = pp[768];
    }

    for (int t = 0; t < S_LEN; ++t) {
        const int s = dir ? (S_LEN - 1 - t) : t;
        if (t) cl_wait();   // h(t) visible

        // z partials with software-pipelined LDS: loads for iter kb+1 issue
        // before FMAs of iter kb consume the previous registers.
        const float* hc = sm + R3_HBUF + cur * 1024;
        const float* wbase = sm + R3_W + (ot << 2);
        const int k0 = kg * 32;
        unsigned long long acc0[4], acc1[4];
#pragma unroll
        for (int b = 0; b < 4; ++b) { acc0[b] = 0ull; acc1[b] = 0ull; }

        float4 h0 = *(const float4*)(hc + k0);
        float4 h1 = *(const float4*)(hc + 256 + k0);
        float4 h2 = *(const float4*)(hc + 512 + k0);
        float4 h3 = *(const float4*)(hc + 768 + k0);
        ulonglong2 w0 = *(const ulonglong2*)(wbase + (k0 + 0) * 128);
        ulonglong2 w1 = *(const ulonglong2*)(wbase + (k0 + 1) * 128);
        ulonglong2 w2 = *(const ulonglong2*)(wbase + (k0 + 2) * 128);
        ulonglong2 w3 = *(const ulonglong2*)(wbase + (k0 + 3) * 128);

#pragma unroll
        for (int kb = 0; kb < 8; ++kb) {
            float4 ch0 = h0, ch1 = h1, ch2 = h2, ch3 = h3;
            ulonglong2 cw0 = w0, cw1 = w1, cw2 = w2, cw3 = w3;
            if (kb < 7) {
                const int kn = k0 + (kb + 1) * 4;
                h0 = *(const float4*)(hc + kn);
                h1 = *(const float4*)(hc + 256 + kn);
                h2 = *(const float4*)(hc + 512 + kn);
                h3 = *(const float4*)(hc + 768 + kn);
                w0 = *(const ulonglong2*)(wbase + (kn + 0) * 128);
                w1 = *(const ulonglong2*)(wbase + (kn + 1) * 128);
                w2 = *(const ulonglong2*)(wbase + (kn + 2) * 128);
                w3 = *(const ulonglong2*)(wbase + (kn + 3) * 128);
            }
            float ha[4][4] = {{ch0.x, ch1.x, ch2.x, ch3.x},
                              {ch0.y, ch1.y, ch2.y, ch3.y},
                              {ch0.z, ch1.z, ch2.z, ch3.z},
                              {ch0.w, ch1.w, ch2.w, ch3.w}};
            ulonglong2 cw[4] = {cw0, cw1, cw2, cw3};
#pragma unroll
            for (int j = 0; j < 4; ++j) {
#pragma unroll
                for (int b = 0; b < 4; ++b) {
                    unsigned long long hs = pk2(ha[j][b], ha[j][b]);
                    fma2(acc0[b], cw[j].x, hs);
                    fma2(acc1[b], cw[j].y, hs);
                }
            }
        }
        {
            float* zb = sm + R3_ZRED + kg * 512 + (ot << 2);
#pragma unroll
            for (int b = 0; b < 4; ++b) {
                ulonglong2 v; v.x = acc0[b]; v.y = acc1[b];
                *(ulonglong2*)(zb + b * 128) = v;
            }
        }
        __syncthreads();

        if (tid < 128) {
            float z0 = pre4[0], z1 = pre4[1], z2 = pre4[2], z3 = pre4[3];
#pragma unroll
            for (int kk = 0; kk < 8; ++kk) {
                const float* zb = sm + R3_ZRED + kk * 512 + gb * 128;
                z0 += zb[guu]; z1 += zb[32 + guu]; z2 += zb[64 + guu]; z3 += zb[96 + guu];
            }
            float ig = sigf(z0), fg = sigf(z1);
            float gg = tanh_ap(z2), og = sigf(z3);
            cstate = fg * cstate + ig * gg;
            float hval = og * tanh_ap(cstate);
            hout[(size_t)(s * BATCH + bglob) * 256 + ((int)r << 5) + guu] = hval;

            float hnext = __shfl_down_sync(0xffffffffu, hval, 1);
            if ((guu & 1) == 0) {
                unsigned long long pk =
                    ((unsigned long long)__float_as_uint(hnext) << 32) | __float_as_uint(hval);
                uint32_t laddr = hbuf_u32 +
                    (uint32_t)(((cur ^ 1) * 1024 + gb * 256 + ((int)r << 5) + guu) * 4);
#pragma unroll
                for (int rr = 0; rr < 8; ++rr) {
                    uint32_t ra;
                    asm("mapa.shared::cluster.u32 %0, %1, %2;" : "=r"(ra) : "r"(laddr), "r"(rr));
                    asm volatile("st.shared::cluster.b64 [%0], %1;" :: "r"(ra), "l"(pk) : "memory");
                }
            }
        }
        cl_arrive();   // releases this CTA's DSMEM stores

        // prefetch next step's pre under the barrier window
        if (tid < 128 && t + 1 < S_LEN) {
            const int s2 = dir ? (S_LEN - 2 - t) : (t + 1);
            const float* pp = preb + (size_t)(s2 * BATCH + bglob) * G4 + ((int)r << 5) + guu;
            pre4[0] = pp[0]; pre4[1] = pp[256]; pre4[2] = pp[512]; pre4[3] = pp[768];
        }
        cur ^= 1;
    }
    cl_wait();   // balance final arrive
}

// ---------------- kernel 4: emissions (256 thr: hf/hb split + smem reduce) ----------------
__global__ void __launch_bounds__(256) k_emit(const float* __restrict__ Wt,
                                              const float* __restrict__ bt) {
    __shared__ float WtT[8192];   // [k][t], 512 x 16
    __shared__ float part[2048];  // 128 rows x 16 tags
    const int tid = threadIdx.x;
    for (int i = tid; i < 8192; i += 256) {
        int k = i >> 4, t = i & 15;
        WtT[i] = Wt[t * 512 + k];
    }
    __syncthreads();

    const int half = tid >> 7, rt = tid & 127;
    const size_t m = (size_t)blockIdx.x * 128 + rt;
    const float4* rr = (const float4*)((half ? g_hb : g_hf) + m * 256);
    const float* wb = &WtT[half * 4096];
    float acc[16];
#pragma unroll
    for (int t = 0; t < 16; ++t) acc[t] = 0.f;

#pragma unroll 4
    for (int k4 = 0; k4 < 64; ++k4) {
        float4 f = rr[k4];
        float fa[4] = {f.x, f.y, f.z, f.w};
#pragma unroll
        for (int j = 0; j < 4; ++j) {
            const float* wrow = &wb[(k4 * 4 + j) * 16];
            float4 w0 = *(const float4*)(wrow + 0);
            float4 w1 = *(const float4*)(wrow + 4);
            float4 w2 = *(const float4*)(wrow + 8);
            float4 w3 = *(const float4*)(wrow + 12);
            acc[0]  += fa[j] * w0.x; acc[1]  += fa[j] * w0.y; acc[2]  += fa[j] * w0.z; acc[3]  += fa[j] * w0.w;
            acc[4]  += fa[j] * w1.x; acc[5]  += fa[j] * w1.y; acc[6]  += fa[j] * w1.z; acc[7]  += fa[j] * w1.w;
            acc[8]  += fa[j] * w2.x; acc[9]  += fa[j] * w2.y; acc[10] += fa[j] * w2.z; acc[11] += fa[j] * w2.w;
            acc[12] += fa[j] * w3.x; acc[13] += fa[j] * w3.y; acc[14] += fa[j] * w3.z; acc[15] += fa[j] * w3.w;
        }
    }
    if (half == 0) {
#pragma unroll
        for (int t = 0; t < 16; t += 4)
            *(float4*)&part[rt * 16 + t] = make_float4(acc[t], acc[t+1], acc[t+2], acc[t+3]);
    }
    __syncthreads();
    if (half == 1) {
        float4* o = (float4*)(g_emit + m * 16);
#pragma unroll
        for (int t = 0; t < 16; t += 4) {
            float4 p = *(const float4*)&part[rt * 16 + t];
            float4 v;
            v.x = acc[t+0] + p.x + bt[t+0];
            v.y = acc[t+1] + p.y + bt[t+1];
            v.z = acc[t+2] + p.z + bt[t+2];
            v.w = acc[t+3] + p.w + bt[t+3];
            o[t >> 2] = v;
        }
    }
}

// ---------------- kernel 5: CRF forward, one block per batch ----------------
__global__ void __launch_bounds__(32) k_crf(const float* __restrict__ trans,
                                            float* __restrict__ out) {
    __shared__ float embuf[512];   // 32 steps x 16 tags
    const int b = blockIdx.x;
    const int lane = threadIdx.x;
    const int tn = lane >> 1;        // target tag
    const int tp0 = (lane & 1) * 8;  // my half of prev tags

    float tr[8];
#pragma unroll
    for (int j = 0; j < 8; ++j) tr[j] = trans[tn * 16 + tp0 + j];

    float al[8];
#pragma unroll
    for (int j = 0; j < 8; ++j) al[j] = ((tp0 + j) == 14) ? 0.f : NEGV;  // START=14

    for (int c = 0; c < 16; ++c) {   // 16 chunks of 32 steps
        for (int i = lane; i < 128; i += 32) {
            int sl = i >> 2, q = i & 3;
            ((float4*)embuf)[i] =
                *(const float4*)(g_emit + ((size_t)((c * 32 + sl) * 32 + b) * 16) + q * 4);
        }
        __syncwarp();

        for (int sl = 0; sl < 32; ++sl) {
            float m8 = -1e30f;
            float sc[8];
#pragma unroll
            for (int j = 0; j < 8; ++j) {
                sc[j] = al[j] + tr[j];
                m8 = fmaxf(m8, sc[j]);
            }
            float m = fmaxf(m8, __shfl_xor_sync(0xffffffffu, m8, 1));
            float e = 0.f;
#pragma unroll
            for (int j = 0; j < 8; ++j) e += __expf(sc[j] - m);
            e += __shfl_xor_sync(0xffffffffu, e, 1);
            float na = m + __logf(e) + embuf[sl * 16 + tn];
#pragma unroll
            for (int j = 0; j < 8; ++j)
                al[j] = __shfl_sync(0xffffffffu, na, (tp0 + j) << 1);
        }
        __syncwarp();
    }

    float m8 = -1e30f;
    float sc[8];
#pragma unroll
    for (int j = 0; j < 8; ++j) {
        sc[j] = al[j] + trans[15 * 16 + tp0 + j];
        m8 = fmaxf(m8, sc[j]);
    }
    float m = fmaxf(m8, __shfl_xor_sync(0xffffffffu, m8, 1));
    float e = 0.f;
#pragma unroll
    for (int j = 0; j < 8; ++j) e += __expf(sc[j] - m);
    e += __shfl_xor_sync(0xffffffffu, e, 1);
    if (lane == 0) out[b] = m + __logf(e);
}

// ---------------- launch ----------------
extern "C" void kernel_launch(void* const* d_in, const int* in_sizes, int n_in,
                              void* d_out, int out_size) {
    (void)in_sizes; (void)n_in; (void)out_size;
    const int*   tokens = (const int*)  d_in[0];
    const float* emb    = (const float*)d_in[1];
    const float* Wi_f   = (const float*)d_in[2];
    const float* Wh_f   = (const float*)d_in[3];
    const float* bi_f   = (const float*)d_in[4];
    const float* bh_f   = (const float*)d_in[5];
    const float* Wi_b   = (const float*)d_in[6];
    const float* Wh_b   = (const float*)d_in[7];
    const float* bi_b   = (const float*)d_in[8];
    const float* bh_b   = (const float*)d_in[9];
    const float* Wt     = (const float*)d_in[10];
    const float* bt     = (const float*)d_in[11];
    const float* trans  = (const float*)d_in[12];
    float* out = (float*)d_out;

    static int configured = 0;
    if (!configured) {
        cudaFuncSetAttribute(k_recur, cudaFuncAttributeMaxDynamicSharedMemorySize, R3_SMEMB);
        configured = 1;
    }

    k_gather<<<MROWS, 64>>>(tokens, emb);
    k_gemm<<<dim3(8, 128, 2), 256>>>(Wi_f, bi_f, bh_f, Wi_b, bi_b, bh_b);
    k_probe<<<1, 32>>>();   // keep k_recur in ncu's profiled slot
    k_recur<<<128, 256, R3_SMEMB>>>(Wh_f, Wh_b);
    k_emit<<<128, 256>>>(Wt, bt);
    k_crf<<<BATCH, 32>>>(trans, out);
}